// round 1
// baseline (speedup 1.0000x reference)
#include <cuda_runtime.h>
#include <cuda_bf16.h>

// Problem constants
#define Bx 4
#define Cx 3
#define Hx 224
#define Wx 224
#define Kx 196
#define Ex 768
#define HW (Hx * Wx)            // 50176
#define POOL_ELEMS (Bx * Kx * Cx)  // 2352

// Scratch: pooled sums (un-normalized)
__device__ float g_pooled[POOL_ELEMS];

__global__ void zero_pooled() {
    int i = blockIdx.x * blockDim.x + threadIdx.x;
    if (i < POOL_ELEMS) g_pooled[i] = 0.0f;
}

// One batch is split over BLOCKS_PER_BATCH blocks; each block accumulates
// K*C partial sums in shared memory, then flushes with global atomics.
#define BLOCKS_PER_BATCH 56
#define THREADS_ACC 256

__global__ void accumulate_kernel(const float* __restrict__ img,
                                  const int* __restrict__ seg) {
    __shared__ float s_pool[Kx * Cx];   // 588 floats

    const int b = blockIdx.x / BLOCKS_PER_BATCH;
    const int blk = blockIdx.x % BLOCKS_PER_BATCH;

    // zero shared
    for (int i = threadIdx.x; i < Kx * Cx; i += THREADS_ACC) s_pool[i] = 0.0f;
    __syncthreads();

    const int pix_per_block = HW / BLOCKS_PER_BATCH;  // 896
    const int pix0 = blk * pix_per_block;

    const float* img_b = img + (size_t)b * Cx * HW;
    const int*   seg_b = seg + (size_t)b * HW;

    for (int p = pix0 + threadIdx.x; p < pix0 + pix_per_block; p += THREADS_ACC) {
        int k = seg_b[p];
        float v0 = img_b[p];
        float v1 = img_b[p + HW];
        float v2 = img_b[p + 2 * HW];
        atomicAdd(&s_pool[k * Cx + 0], v0);
        atomicAdd(&s_pool[k * Cx + 1], v1);
        atomicAdd(&s_pool[k * Cx + 2], v2);
    }
    __syncthreads();

    float* gp = g_pooled + b * Kx * Cx;
    for (int i = threadIdx.x; i < Kx * Cx; i += THREADS_ACC) {
        float v = s_pool[i];
        if (v != 0.0f) atomicAdd(&gp[i], v);
        else atomicAdd(&gp[i], 0.0f);  // keep deterministic path simple; harmless
    }
}

// out[b,k,e] = sum_c (pooled[b,k,c]/HW) * W[c,e] + bias[e]
// One block per (b,k) row, 768 threads covering E.
__global__ void gemm_kernel(const float* __restrict__ Wmat,
                            const float* __restrict__ bias,
                            float* __restrict__ out) {
    const int bk = blockIdx.x;          // 0 .. B*K-1
    const int e  = threadIdx.x;         // 0 .. 767

    const float inv = 1.0f / (float)HW;
    // all threads read the same 3 values -> broadcast from L1
    float p0 = g_pooled[bk * Cx + 0] * inv;
    float p1 = g_pooled[bk * Cx + 1] * inv;
    float p2 = g_pooled[bk * Cx + 2] * inv;

    float acc = bias[e];
    acc += p0 * Wmat[0 * Ex + e];
    acc += p1 * Wmat[1 * Ex + e];
    acc += p2 * Wmat[2 * Ex + e];

    out[(size_t)bk * Ex + e] = acc;
}

extern "C" void kernel_launch(void* const* d_in, const int* in_sizes, int n_in,
                              void* d_out, int out_size) {
    const float* img  = (const float*)d_in[0];
    const int*   seg  = (const int*)d_in[1];
    const float* Wmat = (const float*)d_in[2];
    const float* bias = (const float*)d_in[3];
    float* out = (float*)d_out;

    zero_pooled<<<(POOL_ELEMS + 255) / 256, 256>>>();
    accumulate_kernel<<<Bx * BLOCKS_PER_BATCH, THREADS_ACC>>>(img, seg);
    gemm_kernel<<<Bx * Kx, Ex>>>(Wmat, bias, out);
}